// round 6
// baseline (speedup 1.0000x reference)
#include <cuda_runtime.h>

// Problem shape (fixed by reference): B=4, T=2048, N=1024, H=16, Dh=64
#define B_SZ   4
#define T_SEQ  2048
#define NDIM   1024
#define NH     16
#define DH     64
#define BH_TOT (B_SZ * NH)          // 64
#define M_ROWS (B_SZ * T_SEQ)       // 8192
#define K_DIM  1024

// Scratch (device globals — allocation-free per harness rules). 128 MB total.
__device__ float g_Q[(size_t)BH_TOT * T_SEQ * DH];   // [bh][t][d]
__device__ float g_K[(size_t)BH_TOT * T_SEQ * DH];
__device__ float g_V[(size_t)BH_TOT * T_SEQ * DH];
__device__ float g_Y[(size_t)M_ROWS * NDIM];         // attention output [b*T+t][n]

// ---------------------------------------------------------------------------
// SGEMM: C[M=8192, N] = A[8192,1024] @ W[1024,N] + bias
// MODE 0: A = param, epilogue scatters into g_Q/g_K/g_V ([bh][t][d] layout)
// MODE 1: A = g_Y,  epilogue writes Cout row-major
// 128x128 tile, BK=16, 256 threads, 8x8 micro-tile.
// ---------------------------------------------------------------------------
template <int N, int MODE>
__global__ __launch_bounds__(256, 2)
void sgemm_kernel(const float* __restrict__ A, const float* __restrict__ W,
                  const float* __restrict__ bias, float* __restrict__ Cout)
{
    __shared__ float As[16][128];   // [k][m]
    __shared__ float Bs[16][128];   // [k][n]

    const int tid  = threadIdx.x;
    const int row0 = blockIdx.y * 128;
    const int col0 = blockIdx.x * 128;

    const int aRow = tid >> 2;            // 0..63
    const int aCol = (tid & 3) << 2;      // 0,4,8,12
    const int bRow = tid >> 5;            // 0..7
    const int bCol = (tid & 31) << 2;     // 0..124

    const int ty = tid >> 4;              // 0..15
    const int tx = tid & 15;              // 0..15

    const float* Asrc = (MODE == 0) ? A : (const float*)g_Y;

    float acc[8][8];
#pragma unroll
    for (int i = 0; i < 8; i++)
#pragma unroll
        for (int j = 0; j < 8; j++) acc[i][j] = 0.f;

    const float* Ab = Asrc + (size_t)row0 * K_DIM;
    const float* Wb = W + col0;

    for (int k0 = 0; k0 < K_DIM; k0 += 16) {
#pragma unroll
        for (int i = 0; i < 2; i++) {
            int r = aRow + i * 64;
            float4 v = *(const float4*)(Ab + (size_t)r * K_DIM + (k0 + aCol));
            As[aCol + 0][r] = v.x;
            As[aCol + 1][r] = v.y;
            As[aCol + 2][r] = v.z;
            As[aCol + 3][r] = v.w;
        }
#pragma unroll
        for (int i = 0; i < 2; i++) {
            int r = bRow + i * 8;
            *(float4*)&Bs[r][bCol] = *(const float4*)(Wb + (size_t)(k0 + r) * N + bCol);
        }
        __syncthreads();

#pragma unroll
        for (int kk = 0; kk < 16; kk++) {
            float regM[8], regN[8];
            *(float4*)&regM[0] = *(float4*)&As[kk][ty * 8];
            *(float4*)&regM[4] = *(float4*)&As[kk][ty * 8 + 4];
            *(float4*)&regN[0] = *(float4*)&Bs[kk][tx * 8];
            *(float4*)&regN[4] = *(float4*)&Bs[kk][tx * 8 + 4];
#pragma unroll
            for (int i = 0; i < 8; i++)
#pragma unroll
                for (int j = 0; j < 8; j++)
                    acc[i][j] = fmaf(regM[i], regN[j], acc[i][j]);
        }
        __syncthreads();
    }

    float bv[8];
#pragma unroll
    for (int j = 0; j < 8; j++) bv[j] = bias[col0 + tx * 8 + j];

    if (MODE == 0) {
        // scatter qkv -> g_Q/g_K/g_V in [bh][t][d]
#pragma unroll
        for (int i = 0; i < 8; i++) {
            int r = row0 + ty * 8 + i;
            int b = r >> 11;           // /2048
            int t = r & 2047;
#pragma unroll
            for (int j = 0; j < 8; j++) {
                int c = col0 + tx * 8 + j;
                float v = acc[i][j] + bv[j];
                int which = c >> 10;   // 0=Q 1=K 2=V (uniform per CTA)
                int n = c & 1023;
                int h = n >> 6;
                int d = n & 63;
                size_t idx = (((size_t)(b * NH + h) * T_SEQ) + t) * DH + d;
                float* dst = (which == 0) ? g_Q : (which == 1) ? g_K : g_V;
                dst[idx] = v;
            }
        }
    } else {
#pragma unroll
        for (int i = 0; i < 8; i++) {
            size_t r = row0 + ty * 8 + i;
#pragma unroll
            for (int j = 0; j < 8; j++) {
                int c = col0 + tx * 8 + j;
                Cout[r * N + c] = acc[i][j] + bv[j];
            }
        }
    }
}

// ---------------------------------------------------------------------------
// Causal flash attention, fp32. One CTA per (bh, 64-query tile).
// 256 threads: ty=tid/16 owns 4 query rows, tx=tid%16 owns 4 cols.
// Online softmax; key blocks of 64 up to the causal limit.
// Dynamic smem: Qt[64][68] (d-major), Kt[64][68] (d-major), Vs[64][68], Pt[64][68]
// ---------------------------------------------------------------------------
#define APAD 68
#define ABUF (DH * APAD)                           // floats per buffer
#define ATTN_SMEM (4 * ABUF * (int)sizeof(float))  // 69632 bytes

__global__ __launch_bounds__(256, 3)
void attn_kernel()
{
    extern __shared__ float smem[];
    float* Qt = smem;               // [d][q]
    float* Kt = smem + ABUF;        // [d][k]
    float* Vs = smem + 2 * ABUF;    // [k][d]
    float* Pt = smem + 3 * ABUF;    // [k][q]

    const int tid = threadIdx.x;
    const int qb  = blockIdx.x;     // 0..31
    const int bh  = blockIdx.y;     // 0..63
    const int q0  = qb * 64;

    const float* Qg = g_Q + (size_t)bh * T_SEQ * DH;
    const float* Kg = g_K + (size_t)bh * T_SEQ * DH;
    const float* Vg = g_V + (size_t)bh * T_SEQ * DH;

    // Load Q tile transposed, pre-scaled by 1/sqrt(Dh)=0.125
#pragma unroll
    for (int it = 0; it < 4; it++) {
        int s   = tid + it * 256;    // float4 slot 0..1023
        int row = s >> 4;            // query 0..63
        int c4  = (s & 15) << 2;     // dim 0..60
        float4 v = *(const float4*)(Qg + (size_t)(q0 + row) * DH + c4);
        Qt[(c4 + 0) * APAD + row] = v.x * 0.125f;
        Qt[(c4 + 1) * APAD + row] = v.y * 0.125f;
        Qt[(c4 + 2) * APAD + row] = v.z * 0.125f;
        Qt[(c4 + 3) * APAD + row] = v.w * 0.125f;
    }

    const int ty = tid >> 4;   // q rows ty*4..+4
    const int tx = tid & 15;   // cols tx*4..+4

    float acc[4][4];
    float mrow[4], lrow[4];
#pragma unroll
    for (int i = 0; i < 4; i++) {
        mrow[i] = -1e30f;
        lrow[i] = 0.f;
#pragma unroll
        for (int j = 0; j < 4; j++) acc[i][j] = 0.f;
    }

    for (int jb = 0; jb <= qb; jb++) {
        const int k0 = jb * 64;
        __syncthreads();   // previous PV (reads Vs/Pt) done before reload
#pragma unroll
        for (int it = 0; it < 4; it++) {
            int s   = tid + it * 256;
            int row = s >> 4;
            int c4  = (s & 15) << 2;
            float4 kv = *(const float4*)(Kg + (size_t)(k0 + row) * DH + c4);
            Kt[(c4 + 0) * APAD + row] = kv.x;
            Kt[(c4 + 1) * APAD + row] = kv.y;
            Kt[(c4 + 2) * APAD + row] = kv.z;
            Kt[(c4 + 3) * APAD + row] = kv.w;
            *(float4*)&Vs[row * APAD + c4] =
                *(const float4*)(Vg + (size_t)(k0 + row) * DH + c4);
        }
        __syncthreads();

        // S[4q][4k] = Q K^T (scale already folded into Q)
        float S[4][4];
#pragma unroll
        for (int i = 0; i < 4; i++)
#pragma unroll
            for (int j = 0; j < 4; j++) S[i][j] = 0.f;

#pragma unroll 16
        for (int d = 0; d < DH; d++) {
            float4 qv = *(float4*)&Qt[d * APAD + ty * 4];
            float4 kv = *(float4*)&Kt[d * APAD + tx * 4];
            float qr[4] = {qv.x, qv.y, qv.z, qv.w};
            float kr[4] = {kv.x, kv.y, kv.z, kv.w};
#pragma unroll
            for (int i = 0; i < 4; i++)
#pragma unroll
                for (int j = 0; j < 4; j++)
                    S[i][j] = fmaf(qr[i], kr[j], S[i][j]);
        }

        if (jb == qb) {   // diagonal block: causal mask
#pragma unroll
            for (int i = 0; i < 4; i++)
#pragma unroll
                for (int j = 0; j < 4; j++)
                    if ((k0 + tx * 4 + j) > (q0 + ty * 4 + i)) S[i][j] = -1e30f;
        }

        // Online softmax. Row = 16 threads (same ty) = one 16-lane shfl segment.
#pragma unroll
        for (int i = 0; i < 4; i++) {
            float m = fmaxf(fmaxf(S[i][0], S[i][1]), fmaxf(S[i][2], S[i][3]));
            m = fmaxf(m, __shfl_xor_sync(0xffffffffu, m, 8));
            m = fmaxf(m, __shfl_xor_sync(0xffffffffu, m, 4));
            m = fmaxf(m, __shfl_xor_sync(0xffffffffu, m, 2));
            m = fmaxf(m, __shfl_xor_sync(0xffffffffu, m, 1));
            float mnew = fmaxf(mrow[i], m);
            float corr = __expf(mrow[i] - mnew);
            mrow[i] = mnew;

            float ls = 0.f;
#pragma unroll
            for (int j = 0; j < 4; j++) {
                float p = __expf(S[i][j] - mnew);
                S[i][j] = p;
                ls += p;
            }
            ls += __shfl_xor_sync(0xffffffffu, ls, 8);
            ls += __shfl_xor_sync(0xffffffffu, ls, 4);
            ls += __shfl_xor_sync(0xffffffffu, ls, 2);
            ls += __shfl_xor_sync(0xffffffffu, ls, 1);
            lrow[i] = lrow[i] * corr + ls;

#pragma unroll
            for (int j = 0; j < 4; j++) {
                acc[i][j] *= corr;
                Pt[(tx * 4 + j) * APAD + ty * 4 + i] = S[i][j];
            }
        }
        __syncthreads();

        // O[4q][4d] += P @ V
#pragma unroll 16
        for (int k = 0; k < 64; k++) {
            float4 pv = *(float4*)&Pt[k * APAD + ty * 4];
            float4 vv = *(float4*)&Vs[k * APAD + tx * 4];
            float pr[4] = {pv.x, pv.y, pv.z, pv.w};
            float vr[4] = {vv.x, vv.y, vv.z, vv.w};
#pragma unroll
            for (int i = 0; i < 4; i++)
#pragma unroll
                for (int j = 0; j < 4; j++)
                    acc[i][j] = fmaf(pr[i], vr[j], acc[i][j]);
        }
    }

    // Epilogue: y[b][t][h*64+d] = acc / l
    const int b = bh >> 4;
    const int h = bh & 15;
#pragma unroll
    for (int i = 0; i < 4; i++) {
        float inv = 1.f / lrow[i];
        size_t t = (size_t)q0 + ty * 4 + i;
#pragma unroll
        for (int j = 0; j < 4; j++) {
            g_Y[((size_t)b * T_SEQ + t) * NDIM + h * DH + tx * 4 + j] =
                acc[i][j] * inv;
        }
    }
}

// ---------------------------------------------------------------------------
extern "C" void kernel_launch(void* const* d_in, const int* in_sizes, int n_in,
                              void* d_out, int out_size)
{
    (void)in_sizes; (void)n_in; (void)out_size;
    const float* x      = (const float*)d_in[0];   // [4,2048,1024]
    const float* W_attn = (const float*)d_in[1];   // [1024,3072]
    const float* b_attn = (const float*)d_in[2];   // [3072]
    const float* W_proj = (const float*)d_in[3];   // [1024,1024]
    const float* b_proj = (const float*)d_in[4];   // [1024]
    float* out = (float*)d_out;                    // [4,2048,1024]

    // Host-side attribute set (not a stream op — capture-safe, idempotent)
    cudaFuncSetAttribute(attn_kernel,
                         cudaFuncAttributeMaxDynamicSharedMemorySize, ATTN_SMEM);

    // 1) QKV GEMM + scatter to [bh][t][d]
    sgemm_kernel<3072, 0><<<dim3(3072 / 128, M_ROWS / 128), 256>>>(
        x, W_attn, b_attn, nullptr);

    // 2) Causal flash attention
    attn_kernel<<<dim3(T_SEQ / 64, BH_TOT), 256, ATTN_SMEM>>>();

    // 3) Output projection
    sgemm_kernel<1024, 1><<<dim3(1024 / 128, M_ROWS / 128), 256>>>(
        nullptr, W_proj, b_proj, out);
}

// round 7
// speedup vs baseline: 1.0019x; 1.0019x over previous
#include <cuda_runtime.h>

// Problem shape (fixed by reference): B=4, T=2048, N=1024, H=16, Dh=64
#define B_SZ   4
#define T_SEQ  2048
#define NDIM   1024
#define NH     16
#define DH     64
#define BH_TOT (B_SZ * NH)          // 64
#define M_ROWS (B_SZ * T_SEQ)       // 8192
#define K_DIM  1024

// Scratch (device globals — allocation-free per harness rules). 128 MB total.
__device__ float g_Q[(size_t)BH_TOT * T_SEQ * DH];   // [bh][t][d]
__device__ float g_K[(size_t)BH_TOT * T_SEQ * DH];
__device__ float g_V[(size_t)BH_TOT * T_SEQ * DH];
__device__ float g_Y[(size_t)M_ROWS * NDIM];         // attention output [b*T+t][n]

// ---------------------------------------------------------------------------
// SGEMM: C[M=8192, N] = A[8192,1024] @ W[1024,N] + bias
// MODE 0: A = param, epilogue scatters into g_Q/g_K/g_V ([bh][t][d] layout)
// MODE 1: A = g_Y,  epilogue writes Cout row-major
// 128x128 tile, BK=16, 256 threads, 8x8 micro-tile.
// ---------------------------------------------------------------------------
template <int N, int MODE>
__global__ __launch_bounds__(256, 2)
void sgemm_kernel(const float* __restrict__ A, const float* __restrict__ W,
                  const float* __restrict__ bias, float* __restrict__ Cout)
{
    __shared__ float As[16][128];   // [k][m]
    __shared__ float Bs[16][128];   // [k][n]

    const int tid  = threadIdx.x;
    const int row0 = blockIdx.y * 128;
    const int col0 = blockIdx.x * 128;

    const int aRow = tid >> 2;            // 0..63
    const int aCol = (tid & 3) << 2;      // 0,4,8,12
    const int bRow = tid >> 5;            // 0..7
    const int bCol = (tid & 31) << 2;     // 0..124

    const int ty = tid >> 4;              // 0..15
    const int tx = tid & 15;              // 0..15

    const float* Asrc = (MODE == 0) ? A : (const float*)g_Y;

    float acc[8][8];
#pragma unroll
    for (int i = 0; i < 8; i++)
#pragma unroll
        for (int j = 0; j < 8; j++) acc[i][j] = 0.f;

    const float* Ab = Asrc + (size_t)row0 * K_DIM;
    const float* Wb = W + col0;

    for (int k0 = 0; k0 < K_DIM; k0 += 16) {
#pragma unroll
        for (int i = 0; i < 2; i++) {
            int r = aRow + i * 64;
            float4 v = *(const float4*)(Ab + (size_t)r * K_DIM + (k0 + aCol));
            As[aCol + 0][r] = v.x;
            As[aCol + 1][r] = v.y;
            As[aCol + 2][r] = v.z;
            As[aCol + 3][r] = v.w;
        }
#pragma unroll
        for (int i = 0; i < 2; i++) {
            int r = bRow + i * 8;
            *(float4*)&Bs[r][bCol] = *(const float4*)(Wb + (size_t)(k0 + r) * N + bCol);
        }
        __syncthreads();

#pragma unroll
        for (int kk = 0; kk < 16; kk++) {
            float regM[8], regN[8];
            *(float4*)&regM[0] = *(float4*)&As[kk][ty * 8];
            *(float4*)&regM[4] = *(float4*)&As[kk][ty * 8 + 4];
            *(float4*)&regN[0] = *(float4*)&Bs[kk][tx * 8];
            *(float4*)&regN[4] = *(float4*)&Bs[kk][tx * 8 + 4];
#pragma unroll
            for (int i = 0; i < 8; i++)
#pragma unroll
                for (int j = 0; j < 8; j++)
                    acc[i][j] = fmaf(regM[i], regN[j], acc[i][j]);
        }
        __syncthreads();
    }

    float bv[8];
#pragma unroll
    for (int j = 0; j < 8; j++) bv[j] = bias[col0 + tx * 8 + j];

    if (MODE == 0) {
        // scatter qkv -> g_Q/g_K/g_V in [bh][t][d]
#pragma unroll
        for (int i = 0; i < 8; i++) {
            int r = row0 + ty * 8 + i;
            int b = r >> 11;           // /2048
            int t = r & 2047;
#pragma unroll
            for (int j = 0; j < 8; j++) {
                int c = col0 + tx * 8 + j;
                float v = acc[i][j] + bv[j];
                int which = c >> 10;   // 0=Q 1=K 2=V (uniform per CTA)
                int n = c & 1023;
                int h = n >> 6;
                int d = n & 63;
                size_t idx = (((size_t)(b * NH + h) * T_SEQ) + t) * DH + d;
                float* dst = (which == 0) ? g_Q : (which == 1) ? g_K : g_V;
                dst[idx] = v;
            }
        }
    } else {
#pragma unroll
        for (int i = 0; i < 8; i++) {
            size_t r = row0 + ty * 8 + i;
#pragma unroll
            for (int j = 0; j < 8; j++) {
                int c = col0 + tx * 8 + j;
                Cout[r * N + c] = acc[i][j] + bv[j];
            }
        }
    }
}

// ---------------------------------------------------------------------------
// Causal flash attention, fp32. One CTA per (bh, 64-query tile).
// 256 threads: ty=tid/16 owns 4 query rows, tx=tid%16 owns 4 cols.
// Online softmax; key blocks of 64 up to the causal limit.
// Dynamic smem: Qt[64][68] (d-major), Kt[64][68] (d-major), Vs[64][68], Pt[64][68]
// ---------------------------------------------------------------------------
#define APAD 68
#define ABUF (DH * APAD)                           // floats per buffer
#define ATTN_SMEM (4 * ABUF * (int)sizeof(float))  // 69632 bytes

__global__ __launch_bounds__(256, 3)
void attn_kernel()
{
    extern __shared__ float smem[];
    float* Qt = smem;               // [d][q]
    float* Kt = smem + ABUF;        // [d][k]
    float* Vs = smem + 2 * ABUF;    // [k][d]
    float* Pt = smem + 3 * ABUF;    // [k][q]

    const int tid = threadIdx.x;
    const int qb  = blockIdx.x;     // 0..31
    const int bh  = blockIdx.y;     // 0..63
    const int q0  = qb * 64;

    const float* Qg = g_Q + (size_t)bh * T_SEQ * DH;
    const float* Kg = g_K + (size_t)bh * T_SEQ * DH;
    const float* Vg = g_V + (size_t)bh * T_SEQ * DH;

    // Load Q tile transposed, pre-scaled by 1/sqrt(Dh)=0.125
#pragma unroll
    for (int it = 0; it < 4; it++) {
        int s   = tid + it * 256;    // float4 slot 0..1023
        int row = s >> 4;            // query 0..63
        int c4  = (s & 15) << 2;     // dim 0..60
        float4 v = *(const float4*)(Qg + (size_t)(q0 + row) * DH + c4);
        Qt[(c4 + 0) * APAD + row] = v.x * 0.125f;
        Qt[(c4 + 1) * APAD + row] = v.y * 0.125f;
        Qt[(c4 + 2) * APAD + row] = v.z * 0.125f;
        Qt[(c4 + 3) * APAD + row] = v.w * 0.125f;
    }

    const int ty = tid >> 4;   // q rows ty*4..+4
    const int tx = tid & 15;   // cols tx*4..+4

    float acc[4][4];
    float mrow[4], lrow[4];
#pragma unroll
    for (int i = 0; i < 4; i++) {
        mrow[i] = -1e30f;
        lrow[i] = 0.f;
#pragma unroll
        for (int j = 0; j < 4; j++) acc[i][j] = 0.f;
    }

    for (int jb = 0; jb <= qb; jb++) {
        const int k0 = jb * 64;
        __syncthreads();   // previous PV (reads Vs/Pt) done before reload
#pragma unroll
        for (int it = 0; it < 4; it++) {
            int s   = tid + it * 256;
            int row = s >> 4;
            int c4  = (s & 15) << 2;
            float4 kv = *(const float4*)(Kg + (size_t)(k0 + row) * DH + c4);
            Kt[(c4 + 0) * APAD + row] = kv.x;
            Kt[(c4 + 1) * APAD + row] = kv.y;
            Kt[(c4 + 2) * APAD + row] = kv.z;
            Kt[(c4 + 3) * APAD + row] = kv.w;
            *(float4*)&Vs[row * APAD + c4] =
                *(const float4*)(Vg + (size_t)(k0 + row) * DH + c4);
        }
        __syncthreads();

        // S[4q][4k] = Q K^T (scale already folded into Q)
        float S[4][4];
#pragma unroll
        for (int i = 0; i < 4; i++)
#pragma unroll
            for (int j = 0; j < 4; j++) S[i][j] = 0.f;

#pragma unroll 16
        for (int d = 0; d < DH; d++) {
            float4 qv = *(float4*)&Qt[d * APAD + ty * 4];
            float4 kv = *(float4*)&Kt[d * APAD + tx * 4];
            float qr[4] = {qv.x, qv.y, qv.z, qv.w};
            float kr[4] = {kv.x, kv.y, kv.z, kv.w};
#pragma unroll
            for (int i = 0; i < 4; i++)
#pragma unroll
                for (int j = 0; j < 4; j++)
                    S[i][j] = fmaf(qr[i], kr[j], S[i][j]);
        }

        if (jb == qb) {   // diagonal block: causal mask
#pragma unroll
            for (int i = 0; i < 4; i++)
#pragma unroll
                for (int j = 0; j < 4; j++)
                    if ((k0 + tx * 4 + j) > (q0 + ty * 4 + i)) S[i][j] = -1e30f;
        }

        // Online softmax. Row = 16 threads (same ty) = one 16-lane shfl segment.
#pragma unroll
        for (int i = 0; i < 4; i++) {
            float m = fmaxf(fmaxf(S[i][0], S[i][1]), fmaxf(S[i][2], S[i][3]));
            m = fmaxf(m, __shfl_xor_sync(0xffffffffu, m, 8));
            m = fmaxf(m, __shfl_xor_sync(0xffffffffu, m, 4));
            m = fmaxf(m, __shfl_xor_sync(0xffffffffu, m, 2));
            m = fmaxf(m, __shfl_xor_sync(0xffffffffu, m, 1));
            float mnew = fmaxf(mrow[i], m);
            float corr = __expf(mrow[i] - mnew);
            mrow[i] = mnew;

            float ls = 0.f;
#pragma unroll
            for (int j = 0; j < 4; j++) {
                float p = __expf(S[i][j] - mnew);
                S[i][j] = p;
                ls += p;
            }
            ls += __shfl_xor_sync(0xffffffffu, ls, 8);
            ls += __shfl_xor_sync(0xffffffffu, ls, 4);
            ls += __shfl_xor_sync(0xffffffffu, ls, 2);
            ls += __shfl_xor_sync(0xffffffffu, ls, 1);
            lrow[i] = lrow[i] * corr + ls;

#pragma unroll
            for (int j = 0; j < 4; j++) {
                acc[i][j] *= corr;
                Pt[(tx * 4 + j) * APAD + ty * 4 + i] = S[i][j];
            }
        }
        __syncthreads();

        // O[4q][4d] += P @ V
#pragma unroll 16
        for (int k = 0; k < 64; k++) {
            float4 pv = *(float4*)&Pt[k * APAD + ty * 4];
            float4 vv = *(float4*)&Vs[k * APAD + tx * 4];
            float pr[4] = {pv.x, pv.y, pv.z, pv.w};
            float vr[4] = {vv.x, vv.y, vv.z, vv.w};
#pragma unroll
            for (int i = 0; i < 4; i++)
#pragma unroll
                for (int j = 0; j < 4; j++)
                    acc[i][j] = fmaf(pr[i], vr[j], acc[i][j]);
        }
    }

    // Epilogue: y[b][t][h*64+d] = acc / l
    const int b = bh >> 4;
    const int h = bh & 15;
#pragma unroll
    for (int i = 0; i < 4; i++) {
        float inv = 1.f / lrow[i];
        size_t t = (size_t)q0 + ty * 4 + i;
#pragma unroll
        for (int j = 0; j < 4; j++) {
            g_Y[((size_t)b * T_SEQ + t) * NDIM + h * DH + tx * 4 + j] =
                acc[i][j] * inv;
        }
    }
}

// ---------------------------------------------------------------------------
extern "C" void kernel_launch(void* const* d_in, const int* in_sizes, int n_in,
                              void* d_out, int out_size)
{
    (void)in_sizes; (void)n_in; (void)out_size;
    const float* x      = (const float*)d_in[0];   // [4,2048,1024]
    const float* W_attn = (const float*)d_in[1];   // [1024,3072]
    const float* b_attn = (const float*)d_in[2];   // [3072]
    const float* W_proj = (const float*)d_in[3];   // [1024,1024]
    const float* b_proj = (const float*)d_in[4];   // [1024]
    float* out = (float*)d_out;                    // [4,2048,1024]

    // Host-side attribute set (not a stream op — capture-safe, idempotent)
    cudaFuncSetAttribute(attn_kernel,
                         cudaFuncAttributeMaxDynamicSharedMemorySize, ATTN_SMEM);

    // 1) QKV GEMM + scatter to [bh][t][d]
    sgemm_kernel<3072, 0><<<dim3(3072 / 128, M_ROWS / 128), 256>>>(
        x, W_attn, b_attn, nullptr);

    // 2) Causal flash attention
    attn_kernel<<<dim3(T_SEQ / 64, BH_TOT), 256, ATTN_SMEM>>>();

    // 3) Output projection
    sgemm_kernel<1024, 1><<<dim3(1024 / 128, M_ROWS / 128), 256>>>(
        nullptr, W_proj, b_proj, out);
}

// round 8
// speedup vs baseline: 1.0095x; 1.0076x over previous
#include <cuda_runtime.h>

// Problem shape (fixed by reference): B=4, T=2048, N=1024, H=16, Dh=64
#define B_SZ   4
#define T_SEQ  2048
#define NDIM   1024
#define NH     16
#define DH     64
#define BH_TOT (B_SZ * NH)          // 64
#define M_ROWS (B_SZ * T_SEQ)       // 8192
#define K_DIM  1024

// Scratch (device globals — allocation-free per harness rules). 128 MB total.
__device__ float g_Q[(size_t)BH_TOT * T_SEQ * DH];   // [bh][t][d]
__device__ float g_K[(size_t)BH_TOT * T_SEQ * DH];
__device__ float g_V[(size_t)BH_TOT * T_SEQ * DH];
__device__ float g_Y[(size_t)M_ROWS * NDIM];         // attention output [b*T+t][n]

// ---------------------------------------------------------------------------
// SGEMM: C[M=8192, N] = A[8192,1024] @ W[1024,N] + bias
// MODE 0: A = param, epilogue scatters into g_Q/g_K/g_V ([bh][t][d] layout)
// MODE 1: A = g_Y,  epilogue writes Cout row-major
// 128x128 tile, BK=16, 256 threads, 8x8 micro-tile.
// ---------------------------------------------------------------------------
template <int N, int MODE>
__global__ __launch_bounds__(256, 2)
void sgemm_kernel(const float* __restrict__ A, const float* __restrict__ W,
                  const float* __restrict__ bias, float* __restrict__ Cout)
{
    __shared__ float As[16][128];   // [k][m]
    __shared__ float Bs[16][128];   // [k][n]

    const int tid  = threadIdx.x;
    const int row0 = blockIdx.y * 128;
    const int col0 = blockIdx.x * 128;

    const int aRow = tid >> 2;            // 0..63
    const int aCol = (tid & 3) << 2;      // 0,4,8,12
    const int bRow = tid >> 5;            // 0..7
    const int bCol = (tid & 31) << 2;     // 0..124

    const int ty = tid >> 4;              // 0..15
    const int tx = tid & 15;              // 0..15

    const float* Asrc = (MODE == 0) ? A : (const float*)g_Y;

    float acc[8][8];
#pragma unroll
    for (int i = 0; i < 8; i++)
#pragma unroll
        for (int j = 0; j < 8; j++) acc[i][j] = 0.f;

    const float* Ab = Asrc + (size_t)row0 * K_DIM;
    const float* Wb = W + col0;

    for (int k0 = 0; k0 < K_DIM; k0 += 16) {
#pragma unroll
        for (int i = 0; i < 2; i++) {
            int r = aRow + i * 64;
            float4 v = *(const float4*)(Ab + (size_t)r * K_DIM + (k0 + aCol));
            As[aCol + 0][r] = v.x;
            As[aCol + 1][r] = v.y;
            As[aCol + 2][r] = v.z;
            As[aCol + 3][r] = v.w;
        }
#pragma unroll
        for (int i = 0; i < 2; i++) {
            int r = bRow + i * 8;
            *(float4*)&Bs[r][bCol] = *(const float4*)(Wb + (size_t)(k0 + r) * N + bCol);
        }
        __syncthreads();

#pragma unroll
        for (int kk = 0; kk < 16; kk++) {
            float regM[8], regN[8];
            *(float4*)&regM[0] = *(float4*)&As[kk][ty * 8];
            *(float4*)&regM[4] = *(float4*)&As[kk][ty * 8 + 4];
            *(float4*)&regN[0] = *(float4*)&Bs[kk][tx * 8];
            *(float4*)&regN[4] = *(float4*)&Bs[kk][tx * 8 + 4];
#pragma unroll
            for (int i = 0; i < 8; i++)
#pragma unroll
                for (int j = 0; j < 8; j++)
                    acc[i][j] = fmaf(regM[i], regN[j], acc[i][j]);
        }
        __syncthreads();
    }

    float bv[8];
#pragma unroll
    for (int j = 0; j < 8; j++) bv[j] = bias[col0 + tx * 8 + j];

    if (MODE == 0) {
        // scatter qkv -> g_Q/g_K/g_V in [bh][t][d]
#pragma unroll
        for (int i = 0; i < 8; i++) {
            int r = row0 + ty * 8 + i;
            int b = r >> 11;           // /2048
            int t = r & 2047;
#pragma unroll
            for (int j = 0; j < 8; j++) {
                int c = col0 + tx * 8 + j;
                float v = acc[i][j] + bv[j];
                int which = c >> 10;   // 0=Q 1=K 2=V (uniform per CTA)
                int n = c & 1023;
                int h = n >> 6;
                int d = n & 63;
                size_t idx = (((size_t)(b * NH + h) * T_SEQ) + t) * DH + d;
                float* dst = (which == 0) ? g_Q : (which == 1) ? g_K : g_V;
                dst[idx] = v;
            }
        }
    } else {
#pragma unroll
        for (int i = 0; i < 8; i++) {
            size_t r = row0 + ty * 8 + i;
#pragma unroll
            for (int j = 0; j < 8; j++) {
                int c = col0 + tx * 8 + j;
                Cout[r * N + c] = acc[i][j] + bv[j];
            }
        }
    }
}

// ---------------------------------------------------------------------------
// Causal flash attention, fp32. One CTA per (bh, 64-query tile).
// 256 threads: ty=tid/16 owns 4 query rows, tx=tid%16 owns 4 cols.
// Online softmax; key blocks of 64 up to the causal limit.
// Dynamic smem: Qt[64][68] (d-major), Kt[64][68] (d-major), Vs[64][68], Pt[64][68]
// ---------------------------------------------------------------------------
#define APAD 68
#define ABUF (DH * APAD)                           // floats per buffer
#define ATTN_SMEM (4 * ABUF * (int)sizeof(float))  // 69632 bytes

__global__ __launch_bounds__(256, 3)
void attn_kernel()
{
    extern __shared__ float smem[];
    float* Qt = smem;               // [d][q]
    float* Kt = smem + ABUF;        // [d][k]
    float* Vs = smem + 2 * ABUF;    // [k][d]
    float* Pt = smem + 3 * ABUF;    // [k][q]

    const int tid = threadIdx.x;
    const int qb  = blockIdx.x;     // 0..31
    const int bh  = blockIdx.y;     // 0..63
    const int q0  = qb * 64;

    const float* Qg = g_Q + (size_t)bh * T_SEQ * DH;
    const float* Kg = g_K + (size_t)bh * T_SEQ * DH;
    const float* Vg = g_V + (size_t)bh * T_SEQ * DH;

    // Load Q tile transposed, pre-scaled by 1/sqrt(Dh)=0.125
#pragma unroll
    for (int it = 0; it < 4; it++) {
        int s   = tid + it * 256;    // float4 slot 0..1023
        int row = s >> 4;            // query 0..63
        int c4  = (s & 15) << 2;     // dim 0..60
        float4 v = *(const float4*)(Qg + (size_t)(q0 + row) * DH + c4);
        Qt[(c4 + 0) * APAD + row] = v.x * 0.125f;
        Qt[(c4 + 1) * APAD + row] = v.y * 0.125f;
        Qt[(c4 + 2) * APAD + row] = v.z * 0.125f;
        Qt[(c4 + 3) * APAD + row] = v.w * 0.125f;
    }

    const int ty = tid >> 4;   // q rows ty*4..+4
    const int tx = tid & 15;   // cols tx*4..+4

    float acc[4][4];
    float mrow[4], lrow[4];
#pragma unroll
    for (int i = 0; i < 4; i++) {
        mrow[i] = -1e30f;
        lrow[i] = 0.f;
#pragma unroll
        for (int j = 0; j < 4; j++) acc[i][j] = 0.f;
    }

    for (int jb = 0; jb <= qb; jb++) {
        const int k0 = jb * 64;
        __syncthreads();   // previous PV (reads Vs/Pt) done before reload
#pragma unroll
        for (int it = 0; it < 4; it++) {
            int s   = tid + it * 256;
            int row = s >> 4;
            int c4  = (s & 15) << 2;
            float4 kv = *(const float4*)(Kg + (size_t)(k0 + row) * DH + c4);
            Kt[(c4 + 0) * APAD + row] = kv.x;
            Kt[(c4 + 1) * APAD + row] = kv.y;
            Kt[(c4 + 2) * APAD + row] = kv.z;
            Kt[(c4 + 3) * APAD + row] = kv.w;
            *(float4*)&Vs[row * APAD + c4] =
                *(const float4*)(Vg + (size_t)(k0 + row) * DH + c4);
        }
        __syncthreads();

        // S[4q][4k] = Q K^T (scale already folded into Q)
        float S[4][4];
#pragma unroll
        for (int i = 0; i < 4; i++)
#pragma unroll
            for (int j = 0; j < 4; j++) S[i][j] = 0.f;

#pragma unroll 16
        for (int d = 0; d < DH; d++) {
            float4 qv = *(float4*)&Qt[d * APAD + ty * 4];
            float4 kv = *(float4*)&Kt[d * APAD + tx * 4];
            float qr[4] = {qv.x, qv.y, qv.z, qv.w};
            float kr[4] = {kv.x, kv.y, kv.z, kv.w};
#pragma unroll
            for (int i = 0; i < 4; i++)
#pragma unroll
                for (int j = 0; j < 4; j++)
                    S[i][j] = fmaf(qr[i], kr[j], S[i][j]);
        }

        if (jb == qb) {   // diagonal block: causal mask
#pragma unroll
            for (int i = 0; i < 4; i++)
#pragma unroll
                for (int j = 0; j < 4; j++)
                    if ((k0 + tx * 4 + j) > (q0 + ty * 4 + i)) S[i][j] = -1e30f;
        }

        // Online softmax. Row = 16 threads (same ty) = one 16-lane shfl segment.
#pragma unroll
        for (int i = 0; i < 4; i++) {
            float m = fmaxf(fmaxf(S[i][0], S[i][1]), fmaxf(S[i][2], S[i][3]));
            m = fmaxf(m, __shfl_xor_sync(0xffffffffu, m, 8));
            m = fmaxf(m, __shfl_xor_sync(0xffffffffu, m, 4));
            m = fmaxf(m, __shfl_xor_sync(0xffffffffu, m, 2));
            m = fmaxf(m, __shfl_xor_sync(0xffffffffu, m, 1));
            float mnew = fmaxf(mrow[i], m);
            float corr = __expf(mrow[i] - mnew);
            mrow[i] = mnew;

            float ls = 0.f;
#pragma unroll
            for (int j = 0; j < 4; j++) {
                float p = __expf(S[i][j] - mnew);
                S[i][j] = p;
                ls += p;
            }
            ls += __shfl_xor_sync(0xffffffffu, ls, 8);
            ls += __shfl_xor_sync(0xffffffffu, ls, 4);
            ls += __shfl_xor_sync(0xffffffffu, ls, 2);
            ls += __shfl_xor_sync(0xffffffffu, ls, 1);
            lrow[i] = lrow[i] * corr + ls;

#pragma unroll
            for (int j = 0; j < 4; j++) {
                acc[i][j] *= corr;
                Pt[(tx * 4 + j) * APAD + ty * 4 + i] = S[i][j];
            }
        }
        __syncthreads();

        // O[4q][4d] += P @ V
#pragma unroll 16
        for (int k = 0; k < 64; k++) {
            float4 pv = *(float4*)&Pt[k * APAD + ty * 4];
            float4 vv = *(float4*)&Vs[k * APAD + tx * 4];
            float pr[4] = {pv.x, pv.y, pv.z, pv.w};
            float vr[4] = {vv.x, vv.y, vv.z, vv.w};
#pragma unroll
            for (int i = 0; i < 4; i++)
#pragma unroll
                for (int j = 0; j < 4; j++)
                    acc[i][j] = fmaf(pr[i], vr[j], acc[i][j]);
        }
    }

    // Epilogue: y[b][t][h*64+d] = acc / l
    const int b = bh >> 4;
    const int h = bh & 15;
#pragma unroll
    for (int i = 0; i < 4; i++) {
        float inv = 1.f / lrow[i];
        size_t t = (size_t)q0 + ty * 4 + i;
#pragma unroll
        for (int j = 0; j < 4; j++) {
            g_Y[((size_t)b * T_SEQ + t) * NDIM + h * DH + tx * 4 + j] =
                acc[i][j] * inv;
        }
    }
}

// ---------------------------------------------------------------------------
extern "C" void kernel_launch(void* const* d_in, const int* in_sizes, int n_in,
                              void* d_out, int out_size)
{
    (void)in_sizes; (void)n_in; (void)out_size;
    const float* x      = (const float*)d_in[0];   // [4,2048,1024]
    const float* W_attn = (const float*)d_in[1];   // [1024,3072]
    const float* b_attn = (const float*)d_in[2];   // [3072]
    const float* W_proj = (const float*)d_in[3];   // [1024,1024]
    const float* b_proj = (const float*)d_in[4];   // [1024]
    float* out = (float*)d_out;                    // [4,2048,1024]

    // Host-side attribute set (not a stream op — capture-safe, idempotent)
    cudaFuncSetAttribute(attn_kernel,
                         cudaFuncAttributeMaxDynamicSharedMemorySize, ATTN_SMEM);

    // 1) QKV GEMM + scatter to [bh][t][d]
    sgemm_kernel<3072, 0><<<dim3(3072 / 128, M_ROWS / 128), 256>>>(
        x, W_attn, b_attn, nullptr);

    // 2) Causal flash attention
    attn_kernel<<<dim3(T_SEQ / 64, BH_TOT), 256, ATTN_SMEM>>>();

    // 3) Output projection
    sgemm_kernel<1024, 1><<<dim3(1024 / 128, M_ROWS / 128), 256>>>(
        nullptr, W_proj, b_proj, out);
}